// round 13
// baseline (speedup 1.0000x reference)
#include <cuda_runtime.h>
#include <cuda_fp16.h>
#include <cstdint>

#define Bb 128
#define Tt 1024
#define Dd 256
#define Hh 512
#define Oo 128
#define G4H 2048

#define NG 4      // batch groups (independent LSTM chains)
#define RG 32     // rows per group
#define CG 32     // CTAs per group (each owns 64 gate cols = 16 h cols)

// ---------------- scratch ----------------
__device__ float  g_hf[2][Bb][Hh];            // h double buffer (tf32-rounded fp32)
__device__ float  g_hT[Bb*Hh];                // final h (exact fp32)
__device__ unsigned g_bar4[NG * 4 * 32];      // per-(group,chunk) flags, 128B apart

// ---------------- PTX helpers ----------------
__device__ __forceinline__ unsigned smem_u32(const void* p) {
    return (unsigned)__cvta_generic_to_shared(p);
}
#define CPA16(dst, src) asm volatile("cp.async.cg.shared.global [%0], [%1], 16;\n" :: "r"(dst), "l"(src))
#define CPA_COMMIT()    asm volatile("cp.async.commit_group;\n")
#define CPA_WAIT(n)     asm volatile("cp.async.wait_group %0;\n" :: "n"(n))

__device__ __forceinline__ void ldm_x4(uint32_t* r, unsigned addr) {
    asm volatile("ldmatrix.sync.aligned.m8n8.x4.shared.b16 {%0,%1,%2,%3}, [%4];"
                 : "=r"(r[0]), "=r"(r[1]), "=r"(r[2]), "=r"(r[3]) : "r"(addr));
}
__device__ __forceinline__ void mma_tf32(float* c, const uint32_t* a, uint32_t b0, uint32_t b1) {
    asm volatile("mma.sync.aligned.m16n8k8.row.col.f32.tf32.tf32.f32 "
                 "{%0,%1,%2,%3}, {%4,%5,%6,%7}, {%8,%9}, {%0,%1,%2,%3};"
                 : "+f"(c[0]), "+f"(c[1]), "+f"(c[2]), "+f"(c[3])
                 : "r"(a[0]), "r"(a[1]), "r"(a[2]), "r"(a[3]), "r"(b0), "r"(b1));
}
__device__ __forceinline__ uint32_t tf32_bits(float f) {
    uint32_t u; asm("cvt.rna.tf32.f32 %0, %1;" : "=r"(u) : "f"(f)); return u;
}
__device__ __forceinline__ float tf32_round(float f) { return __uint_as_float(tf32_bits(f)); }
__device__ __forceinline__ unsigned ld_acq(const unsigned* p) {
    unsigned v; asm volatile("ld.acquire.gpu.u32 %0, [%1];" : "=r"(v) : "l"(p) : "memory"); return v;
}
__device__ __forceinline__ void red_rel(unsigned* p, unsigned v) {
    asm volatile("red.release.gpu.add.u32 [%0], %1;" :: "l"(p), "r"(v) : "memory");
}
__device__ __forceinline__ float fsig(float x)  { return 1.f / (1.f + __expf(-x)); }
__device__ __forceinline__ float ftanh(float x) { return 2.f / (1.f + __expf(-2.f * x)) - 1.f; }

// ---------------- fused LSTM: x-projection + recurrence in one persistent kernel ------
// 4 groups x 32 CTAs. CTA: M=32 rows, N=64 gate cols.
// Per warp (kc = wid>>1, tau = wid&1):
//   x-GEMM  : K-slice [kc*64, kc*64+64) of D=256, N-half tau  (runs BEFORE the h spin,
//             A-frags straight from gmem via __ldg + cvt.rna — fully latency-hidden)
//   h-GEMM  : K-chunk [kc*128, kc*128+128) of H=512, N-half tau (critical path)
// Both accumulate into the same registers; K-partials reduced via pbuf as before.
#define S2 516   // fp32 row stride for h smem: 129 x 16B chunks (odd)
#define PB 68    // pbuf padded row stride
__global__ void __launch_bounds__(256, 1) k_rec(const float* __restrict__ x,
                                                const float* __restrict__ Wx,
                                                const float* __restrict__ Wh,
                                                const float* __restrict__ bx,
                                                const float* __restrict__ bh) {
    extern __shared__ char sm[];
    float* hb   = (float*)sm;                      // [32][516]      66048 B
    float* pbuf = hb + RG * S2;                    // [4][32][68]    34816 B
    char*  whb  = (char*)(pbuf + 4 * 32 * PB);     // Wh frags 8 x 8192 = 65536 B
    char*  wxb  = whb + 8 * 8192;                  // Wx frags 8 x 6144 = 49152 B
    const int tid = threadIdx.x, lane = tid & 31, wid = tid >> 5;
    const int kc = wid >> 1, tau = wid & 1;        // K-chunk, N-half of this warp
    const int grp = blockIdx.x >> 5, cn = blockIdx.x & 31;
    const int colbase = cn * 16, row0 = grp * RG;
    unsigned* flags  = &g_bar4[grp * 4 * 32];
    unsigned* myflag = &flags[(cn >> 3) * 32];     // chunk this CTA's h slice feeds
    unsigned* kflag  = &flags[kc * 32];            // chunk this warp consumes

    // ---- build Wh B-fragments (tf32): kl 0..7 -> smem, kl 8..15 -> regs ----
    uint4 breg[16];
    char* wb = whb + wid * 8192;
    for (int kl = 0; kl < 16; kl++) {
        #pragma unroll
        for (int h2 = 0; h2 < 2; h2++) {
            uint32_t v[4];
            #pragma unroll
            for (int q = 0; q < 2; q++) {
                int nt = h2 * 2 + q;
                int n = tau * 32 + nt * 8 + (lane >> 2);  // local gate col 0..63
                int jj = n >> 2, gate = n & 3;
                int grow = gate * Hh + colbase + jj;      // Wh global row
                int k = kc * 128 + kl * 8 + (lane & 3);
                const float* wp = Wh + (size_t)grow * Hh;
                v[q*2]   = tf32_bits(wp[k]);
                v[q*2+1] = tf32_bits(wp[k + 4]);
            }
            uint4 u = make_uint4(v[0], v[1], v[2], v[3]);
            if (kl < 8) *(uint4*)(wb + (kl * 2 + h2) * 512 + lane * 16) = u;
            else breg[(kl - 8) * 2 + h2] = u;
        }
    }
    // ---- build Wx B-fragments (tf32): kl 0..5 -> smem, kl 6..7 -> regs ----
    uint4 xreg[4];
    char* xb = wxb + wid * 6144;
    for (int kl = 0; kl < 8; kl++) {
        #pragma unroll
        for (int h2 = 0; h2 < 2; h2++) {
            uint32_t v[4];
            #pragma unroll
            for (int q = 0; q < 2; q++) {
                int nt = h2 * 2 + q;
                int n = tau * 32 + nt * 8 + (lane >> 2);
                int jj = n >> 2, gate = n & 3;
                int grow = gate * Hh + colbase + jj;      // Wx global row (4H x D)
                int k = kc * 64 + kl * 8 + (lane & 3);
                const float* wp = Wx + (size_t)grow * Dd;
                v[q*2]   = tf32_bits(wp[k]);
                v[q*2+1] = tf32_bits(wp[k + 4]);
            }
            uint4 u = make_uint4(v[0], v[1], v[2], v[3]);
            if (kl < 6) *(uint4*)(xb + (kl * 2 + h2) * 512 + lane * 16) = u;
            else xreg[(kl - 6) * 2 + h2] = u;
        }
    }
    // ---- per-thread epilogue bias (bx+bh), loaded once ----
    float bias[2][4];
    #pragma unroll
    for (int s = 0; s < 2; s++) {
        int j = colbase + ((tid + s * 256) & 15);
        #pragma unroll
        for (int gt = 0; gt < 4; gt++)
            bias[s][gt] = __ldg(&bx[gt * Hh + j]) + __ldg(&bh[gt * Hh + j]);
    }
    // ---- x row pointers for this warp's A-fragments ----
    const size_t TD = (size_t)Tt * Dd;
    const float* xrow[4];
    #pragma unroll
    for (int mq = 0; mq < 4; mq++)
        xrow[mq] = x + (size_t)(row0 + mq * 8 + (lane >> 2)) * TD + (size_t)(lane & 3);

    // zero h0 slice, publish chunk readiness
    for (int tk = tid; tk < 512; tk += 256)
        g_hf[0][row0 + (tk >> 4)][colbase + (tk & 15)] = 0.f;
    __syncthreads();
    if (tid == 0) red_rel(myflag, 1u);

    float cst[2] = {0.f, 0.f};                     // c-state per epilogue task

    for (int t = 0; t < Tt; t++) {
        // ---- x-GEMM: acc = x_t @ Wx^T (K-slice kc*64..+64) — independent of h,
        //      executes in the window where we'd otherwise spin ----
        float acc[2][4][4] = {};
        const size_t toff = (size_t)t * Dd;
        #pragma unroll
        for (int kl = 0; kl < 8; kl++) {
            int k = kc * 64 + kl * 8;
            uint32_t a0[4], a1[4];
            a0[0] = tf32_bits(__ldg(xrow[0] + toff + k));
            a0[1] = tf32_bits(__ldg(xrow[1] + toff + k));
            a0[2] = tf32_bits(__ldg(xrow[0] + toff + k + 4));
            a0[3] = tf32_bits(__ldg(xrow[1] + toff + k + 4));
            a1[0] = tf32_bits(__ldg(xrow[2] + toff + k));
            a1[1] = tf32_bits(__ldg(xrow[3] + toff + k));
            a1[2] = tf32_bits(__ldg(xrow[2] + toff + k + 4));
            a1[3] = tf32_bits(__ldg(xrow[3] + toff + k + 4));
            uint4 q0, q1;
            if (kl < 6) {
                q0 = *(const uint4*)(xb + (kl * 2 + 0) * 512 + lane * 16);
                q1 = *(const uint4*)(xb + (kl * 2 + 1) * 512 + lane * 16);
            } else {
                q0 = xreg[(kl - 6) * 2];
                q1 = xreg[(kl - 6) * 2 + 1];
            }
            mma_tf32(acc[0][0], a0, q0.x, q0.y);
            mma_tf32(acc[0][1], a0, q0.z, q0.w);
            mma_tf32(acc[0][2], a0, q1.x, q1.y);
            mma_tf32(acc[0][3], a0, q1.z, q1.w);
            mma_tf32(acc[1][0], a1, q0.x, q0.y);
            mma_tf32(acc[1][1], a1, q0.z, q0.w);
            mma_tf32(acc[1][2], a1, q1.x, q1.y);
            mma_tf32(acc[1][3], a1, q1.z, q1.w);
        }
        // ---- per-warp spin: only this warp's K-chunk producers (8 CTAs) ----
        if (lane == 0) {
            unsigned tgt = 8u * (unsigned)(t + 1);
            while (ld_acq(kflag) < tgt) {}
        }
        __syncwarp();
        // ---- stage this warp's half of h chunk kc (8 KB); partner-sync ----
        {
            const float* hsrc = &g_hf[t & 1][row0][0];
            #pragma unroll
            for (int i = 0; i < 16; i++) {
                int row = i * 2 + (lane >> 4);
                int cw = kc * 128 + (tau * 16 + (lane & 15)) * 4;
                CPA16(smem_u32(hb + row * S2 + cw), hsrc + (size_t)row * Hh + cw);
            }
            CPA_COMMIT(); CPA_WAIT(0);
            asm volatile("bar.sync %0, 64;" :: "r"(1 + kc) : "memory");
        }
        // ---- h-GEMM: M32 x N32(tau) x K128(kc), accumulate onto x-part ----
        #pragma unroll
        for (int kl = 0; kl < 16; kl++) {
            uint4 q0, q1;
            if (kl < 8) {
                q0 = *(const uint4*)(wb + (kl * 2 + 0) * 512 + lane * 16);
                q1 = *(const uint4*)(wb + (kl * 2 + 1) * 512 + lane * 16);
            } else {
                q0 = breg[(kl - 8) * 2];
                q1 = breg[(kl - 8) * 2 + 1];
            }
            uint32_t a0[4], a1[4];
            int c = kc * 128 + kl * 8 + (lane >> 4) * 4;
            int rr = (lane & 7) + ((lane >> 3) & 1) * 8;
            ldm_x4(a0, smem_u32(hb + rr * S2 + c));
            ldm_x4(a1, smem_u32(hb + (rr + 16) * S2 + c));
            mma_tf32(acc[0][0], a0, q0.x, q0.y);
            mma_tf32(acc[0][1], a0, q0.z, q0.w);
            mma_tf32(acc[0][2], a0, q1.x, q1.y);
            mma_tf32(acc[0][3], a0, q1.z, q1.w);
            mma_tf32(acc[1][0], a1, q0.x, q0.y);
            mma_tf32(acc[1][1], a1, q0.z, q0.w);
            mma_tf32(acc[1][2], a1, q1.x, q1.y);
            mma_tf32(acc[1][3], a1, q1.z, q1.w);
        }
        // ---- store K-partials in logical (row, gatecol) layout ----
        #pragma unroll
        for (int mt = 0; mt < 2; mt++) {
            #pragma unroll
            for (int nt = 0; nt < 4; nt++) {
                int r = mt * 16 + (lane >> 2);
                int n = tau * 32 + nt * 8 + (lane & 3) * 2;
                *(float2*)&pbuf[(kc * 32 + r) * PB + n] =
                    make_float2(acc[mt][nt][0], acc[mt][nt][1]);
                *(float2*)&pbuf[(kc * 32 + r + 8) * PB + n] =
                    make_float2(acc[mt][nt][2], acc[mt][nt][3]);
            }
        }
        __syncthreads();
        // ---- reduce 4 K-partials + bias, LSTM cell update, publish h_{t+1} ----
        #pragma unroll
        for (int s = 0; s < 2; s++) {
            int tk = tid + s * 256;
            int row = tk >> 4, j = tk & 15;
            float4 sum = *(float4*)&pbuf[row * PB + j * 4];
            #pragma unroll
            for (int k = 1; k < 4; k++) {
                float4 p = *(float4*)&pbuf[(k * 32 + row) * PB + j * 4];
                sum.x += p.x; sum.y += p.y; sum.z += p.z; sum.w += p.w;
            }
            float pi = sum.x + bias[s][0];
            float pf = sum.y + bias[s][1];
            float pg = sum.z + bias[s][2];
            float po = sum.w + bias[s][3];
            float ii = fsig(pi), ff = fsig(pf), gg = ftanh(pg), oo = fsig(po);
            float cc = cst[s] * ff + ii * gg;
            cst[s] = cc;
            float hn = oo * ftanh(cc);
            g_hf[(t + 1) & 1][row0 + row][colbase + j] = tf32_round(hn);
            if (t == Tt - 1) g_hT[(row0 + row) * Hh + colbase + j] = hn;  // exact
        }
        __syncthreads();                 // all publishes done before release
        if (tid == 0) red_rel(myflag, 1u);
    }
    // reset group flags for deterministic graph replay
    if (cn == 0 && tid == 0) {
        unsigned fin = 8u * (unsigned)(Tt + 1);
        for (int ch = 0; ch < 4; ch++) {
            while (ld_acq(&flags[ch * 32]) < fin) {}
            *(volatile unsigned*)&flags[ch * 32] = 0u;
        }
        __threadfence();
    }
}

// ---------------- phase 3: out = hT @ Wfc^T + bfc, plus hT copy ----------------
__global__ void k_fc(const float* __restrict__ Wfc, const float* __restrict__ bfc,
                     float* __restrict__ out, int out_size) {
    int gid = blockIdx.x * blockDim.x + threadIdx.x;
    int nthr = gridDim.x * blockDim.x;
    for (int i = gid; i < Bb * Hh && i < out_size; i += nthr) out[i] = g_hT[i];
    if (gid < Bb * Oo) {
        int b = gid >> 7, o = gid & 127;
        const float4* hp = (const float4*)&g_hT[b * Hh];
        const float4* wp = (const float4*)&Wfc[(size_t)o * Hh];
        float s = 0.f;
        #pragma unroll 8
        for (int k = 0; k < Hh / 4; k++) {
            float4 hv = hp[k], wv = wp[k];
            s += hv.x * wv.x + hv.y * wv.y + hv.z * wv.z + hv.w * wv.w;
        }
        int idx = Bb * Hh + gid;
        if (idx < out_size) out[idx] = s + bfc[o];
    }
}

// ---------------- launch ----------------
extern "C" void kernel_launch(void* const* d_in, const int* in_sizes, int n_in,
                              void* d_out, int out_size) {
    const float* x   = (const float*)d_in[0];
    const float* Wx  = (const float*)d_in[2];
    const float* bx  = (const float*)d_in[3];
    const float* Wh  = (const float*)d_in[4];
    const float* bh  = (const float*)d_in[5];
    const float* Wfc = (const float*)d_in[8];
    const float* bfc = (const float*)d_in[9];
    float* out = (float*)d_out;

    // 66048 + 34816 + 65536 + 49152 = 215,552 B
    const int smem_rec = RG * S2 * 4 + 4 * 32 * PB * 4 + 8 * 8192 + 8 * 6144;
    cudaFuncSetAttribute(k_rec, cudaFuncAttributeMaxDynamicSharedMemorySize, smem_rec);

    k_rec<<<NG * CG, 256, smem_rec>>>(x, Wx, Wh, bx, bh);
    k_fc<<<256, 256>>>(Wfc, bfc, out, out_size);
}

// round 14
// speedup vs baseline: 1.0001x; 1.0001x over previous
#include <cuda_runtime.h>
#include <cuda_fp16.h>
#include <cstdint>

#define Bb 128
#define Tt 1024
#define Dd 256
#define Hh 512
#define Oo 128
#define G4H 2048

#define NG 4      // batch groups (independent LSTM chains)
#define RG 32     // rows per group
#define CG 32     // CTAs per group (each owns 64 gate cols = 16 h cols)

// ---------------- scratch ----------------
__device__ float  g_hf[2][Bb][Hh];            // h double buffer (tf32-rounded fp32)
__device__ float  g_hT[Bb*Hh];                // final h (exact fp32)
__device__ unsigned g_bar4[NG * 4 * 32];      // per-(group,chunk) flags, 128B apart

// ---------------- PTX helpers ----------------
__device__ __forceinline__ unsigned smem_u32(const void* p) {
    return (unsigned)__cvta_generic_to_shared(p);
}
#define CPA16(dst, src) asm volatile("cp.async.cg.shared.global [%0], [%1], 16;\n" :: "r"(dst), "l"(src))
#define CPA_COMMIT()    asm volatile("cp.async.commit_group;\n")
#define CPA_WAIT(n)     asm volatile("cp.async.wait_group %0;\n" :: "n"(n))

__device__ __forceinline__ void ldm_x4(uint32_t* r, unsigned addr) {
    asm volatile("ldmatrix.sync.aligned.m8n8.x4.shared.b16 {%0,%1,%2,%3}, [%4];"
                 : "=r"(r[0]), "=r"(r[1]), "=r"(r[2]), "=r"(r[3]) : "r"(addr));
}
__device__ __forceinline__ void mma_tf32(float* c, const uint32_t* a, uint32_t b0, uint32_t b1) {
    asm volatile("mma.sync.aligned.m16n8k8.row.col.f32.tf32.tf32.f32 "
                 "{%0,%1,%2,%3}, {%4,%5,%6,%7}, {%8,%9}, {%0,%1,%2,%3};"
                 : "+f"(c[0]), "+f"(c[1]), "+f"(c[2]), "+f"(c[3])
                 : "r"(a[0]), "r"(a[1]), "r"(a[2]), "r"(a[3]), "r"(b0), "r"(b1));
}
__device__ __forceinline__ uint32_t tf32_bits(float f) {
    uint32_t u; asm("cvt.rna.tf32.f32 %0, %1;" : "=r"(u) : "f"(f)); return u;
}
__device__ __forceinline__ float tf32_round(float f) { return __uint_as_float(tf32_bits(f)); }
__device__ __forceinline__ unsigned ld_acq(const unsigned* p) {
    unsigned v; asm volatile("ld.acquire.gpu.u32 %0, [%1];" : "=r"(v) : "l"(p) : "memory"); return v;
}
__device__ __forceinline__ void red_rel(unsigned* p, unsigned v) {
    asm volatile("red.release.gpu.add.u32 [%0], %1;" :: "l"(p), "r"(v) : "memory");
}
__device__ __forceinline__ float fsig(float x)  { return 1.f / (1.f + __expf(-x)); }
__device__ __forceinline__ float ftanh(float x) { return 2.f / (1.f + __expf(-2.f * x)) - 1.f; }

// ---------------- fused LSTM: x-projection + recurrence in one persistent kernel ------
// 4 groups x 32 CTAs. CTA: M=32 rows, N=64 gate cols.
// Per warp (kc = wid>>1, tau = wid&1):
//   x-GEMM  : K-slice [kc*64, kc*64+64) of D=256, N-half tau  (runs BEFORE the h spin,
//             A-frags straight from gmem via __ldg + cvt.rna — fully latency-hidden)
//   h-GEMM  : K-chunk [kc*128, kc*128+128) of H=512, N-half tau (critical path)
// Both accumulate into the same registers; K-partials reduced via pbuf as before.
#define S2 516   // fp32 row stride for h smem: 129 x 16B chunks (odd)
#define PB 68    // pbuf padded row stride
__global__ void __launch_bounds__(256, 1) k_rec(const float* __restrict__ x,
                                                const float* __restrict__ Wx,
                                                const float* __restrict__ Wh,
                                                const float* __restrict__ bx,
                                                const float* __restrict__ bh) {
    extern __shared__ char sm[];
    float* hb   = (float*)sm;                      // [32][516]      66048 B
    float* pbuf = hb + RG * S2;                    // [4][32][68]    34816 B
    char*  whb  = (char*)(pbuf + 4 * 32 * PB);     // Wh frags 8 x 8192 = 65536 B
    char*  wxb  = whb + 8 * 8192;                  // Wx frags 8 x 6144 = 49152 B
    const int tid = threadIdx.x, lane = tid & 31, wid = tid >> 5;
    const int kc = wid >> 1, tau = wid & 1;        // K-chunk, N-half of this warp
    const int grp = blockIdx.x >> 5, cn = blockIdx.x & 31;
    const int colbase = cn * 16, row0 = grp * RG;
    unsigned* flags  = &g_bar4[grp * 4 * 32];
    unsigned* myflag = &flags[(cn >> 3) * 32];     // chunk this CTA's h slice feeds
    unsigned* kflag  = &flags[kc * 32];            // chunk this warp consumes

    // ---- build Wh B-fragments (tf32): kl 0..7 -> smem, kl 8..15 -> regs ----
    uint4 breg[16];
    char* wb = whb + wid * 8192;
    for (int kl = 0; kl < 16; kl++) {
        #pragma unroll
        for (int h2 = 0; h2 < 2; h2++) {
            uint32_t v[4];
            #pragma unroll
            for (int q = 0; q < 2; q++) {
                int nt = h2 * 2 + q;
                int n = tau * 32 + nt * 8 + (lane >> 2);  // local gate col 0..63
                int jj = n >> 2, gate = n & 3;
                int grow = gate * Hh + colbase + jj;      // Wh global row
                int k = kc * 128 + kl * 8 + (lane & 3);
                const float* wp = Wh + (size_t)grow * Hh;
                v[q*2]   = tf32_bits(wp[k]);
                v[q*2+1] = tf32_bits(wp[k + 4]);
            }
            uint4 u = make_uint4(v[0], v[1], v[2], v[3]);
            if (kl < 8) *(uint4*)(wb + (kl * 2 + h2) * 512 + lane * 16) = u;
            else breg[(kl - 8) * 2 + h2] = u;
        }
    }
    // ---- build Wx B-fragments (tf32): kl 0..5 -> smem, kl 6..7 -> regs ----
    uint4 xreg[4];
    char* xb = wxb + wid * 6144;
    for (int kl = 0; kl < 8; kl++) {
        #pragma unroll
        for (int h2 = 0; h2 < 2; h2++) {
            uint32_t v[4];
            #pragma unroll
            for (int q = 0; q < 2; q++) {
                int nt = h2 * 2 + q;
                int n = tau * 32 + nt * 8 + (lane >> 2);
                int jj = n >> 2, gate = n & 3;
                int grow = gate * Hh + colbase + jj;      // Wx global row (4H x D)
                int k = kc * 64 + kl * 8 + (lane & 3);
                const float* wp = Wx + (size_t)grow * Dd;
                v[q*2]   = tf32_bits(wp[k]);
                v[q*2+1] = tf32_bits(wp[k + 4]);
            }
            uint4 u = make_uint4(v[0], v[1], v[2], v[3]);
            if (kl < 6) *(uint4*)(xb + (kl * 2 + h2) * 512 + lane * 16) = u;
            else xreg[(kl - 6) * 2 + h2] = u;
        }
    }
    // ---- per-thread epilogue bias (bx+bh), loaded once ----
    float bias[2][4];
    #pragma unroll
    for (int s = 0; s < 2; s++) {
        int j = colbase + ((tid + s * 256) & 15);
        #pragma unroll
        for (int gt = 0; gt < 4; gt++)
            bias[s][gt] = __ldg(&bx[gt * Hh + j]) + __ldg(&bh[gt * Hh + j]);
    }
    // ---- x row pointers for this warp's A-fragments ----
    const size_t TD = (size_t)Tt * Dd;
    const float* xrow[4];
    #pragma unroll
    for (int mq = 0; mq < 4; mq++)
        xrow[mq] = x + (size_t)(row0 + mq * 8 + (lane >> 2)) * TD + (size_t)(lane & 3);

    // zero h0 slice, publish chunk readiness
    for (int tk = tid; tk < 512; tk += 256)
        g_hf[0][row0 + (tk >> 4)][colbase + (tk & 15)] = 0.f;
    __syncthreads();
    if (tid == 0) red_rel(myflag, 1u);

    float cst[2] = {0.f, 0.f};                     // c-state per epilogue task

    for (int t = 0; t < Tt; t++) {
        // ---- x-GEMM: acc = x_t @ Wx^T (K-slice kc*64..+64) — independent of h,
        //      executes in the window where we'd otherwise spin ----
        float acc[2][4][4] = {};
        const size_t toff = (size_t)t * Dd;
        #pragma unroll
        for (int kl = 0; kl < 8; kl++) {
            int k = kc * 64 + kl * 8;
            uint32_t a0[4], a1[4];
            a0[0] = tf32_bits(__ldg(xrow[0] + toff + k));
            a0[1] = tf32_bits(__ldg(xrow[1] + toff + k));
            a0[2] = tf32_bits(__ldg(xrow[0] + toff + k + 4));
            a0[3] = tf32_bits(__ldg(xrow[1] + toff + k + 4));
            a1[0] = tf32_bits(__ldg(xrow[2] + toff + k));
            a1[1] = tf32_bits(__ldg(xrow[3] + toff + k));
            a1[2] = tf32_bits(__ldg(xrow[2] + toff + k + 4));
            a1[3] = tf32_bits(__ldg(xrow[3] + toff + k + 4));
            uint4 q0, q1;
            if (kl < 6) {
                q0 = *(const uint4*)(xb + (kl * 2 + 0) * 512 + lane * 16);
                q1 = *(const uint4*)(xb + (kl * 2 + 1) * 512 + lane * 16);
            } else {
                q0 = xreg[(kl - 6) * 2];
                q1 = xreg[(kl - 6) * 2 + 1];
            }
            mma_tf32(acc[0][0], a0, q0.x, q0.y);
            mma_tf32(acc[0][1], a0, q0.z, q0.w);
            mma_tf32(acc[0][2], a0, q1.x, q1.y);
            mma_tf32(acc[0][3], a0, q1.z, q1.w);
            mma_tf32(acc[1][0], a1, q0.x, q0.y);
            mma_tf32(acc[1][1], a1, q0.z, q0.w);
            mma_tf32(acc[1][2], a1, q1.x, q1.y);
            mma_tf32(acc[1][3], a1, q1.z, q1.w);
        }
        // ---- per-warp spin: only this warp's K-chunk producers (8 CTAs) ----
        if (lane == 0) {
            unsigned tgt = 8u * (unsigned)(t + 1);
            while (ld_acq(kflag) < tgt) {}
        }
        __syncwarp();
        // ---- stage this warp's half of h chunk kc (8 KB); partner-sync ----
        {
            const float* hsrc = &g_hf[t & 1][row0][0];
            #pragma unroll
            for (int i = 0; i < 16; i++) {
                int row = i * 2 + (lane >> 4);
                int cw = kc * 128 + (tau * 16 + (lane & 15)) * 4;
                CPA16(smem_u32(hb + row * S2 + cw), hsrc + (size_t)row * Hh + cw);
            }
            CPA_COMMIT(); CPA_WAIT(0);
            asm volatile("bar.sync %0, 64;" :: "r"(1 + kc) : "memory");
        }
        // ---- h-GEMM: M32 x N32(tau) x K128(kc), accumulate onto x-part ----
        #pragma unroll
        for (int kl = 0; kl < 16; kl++) {
            uint4 q0, q1;
            if (kl < 8) {
                q0 = *(const uint4*)(wb + (kl * 2 + 0) * 512 + lane * 16);
                q1 = *(const uint4*)(wb + (kl * 2 + 1) * 512 + lane * 16);
            } else {
                q0 = breg[(kl - 8) * 2];
                q1 = breg[(kl - 8) * 2 + 1];
            }
            uint32_t a0[4], a1[4];
            int c = kc * 128 + kl * 8 + (lane >> 4) * 4;
            int rr = (lane & 7) + ((lane >> 3) & 1) * 8;
            ldm_x4(a0, smem_u32(hb + rr * S2 + c));
            ldm_x4(a1, smem_u32(hb + (rr + 16) * S2 + c));
            mma_tf32(acc[0][0], a0, q0.x, q0.y);
            mma_tf32(acc[0][1], a0, q0.z, q0.w);
            mma_tf32(acc[0][2], a0, q1.x, q1.y);
            mma_tf32(acc[0][3], a0, q1.z, q1.w);
            mma_tf32(acc[1][0], a1, q0.x, q0.y);
            mma_tf32(acc[1][1], a1, q0.z, q0.w);
            mma_tf32(acc[1][2], a1, q1.x, q1.y);
            mma_tf32(acc[1][3], a1, q1.z, q1.w);
        }
        // ---- store K-partials in logical (row, gatecol) layout ----
        #pragma unroll
        for (int mt = 0; mt < 2; mt++) {
            #pragma unroll
            for (int nt = 0; nt < 4; nt++) {
                int r = mt * 16 + (lane >> 2);
                int n = tau * 32 + nt * 8 + (lane & 3) * 2;
                *(float2*)&pbuf[(kc * 32 + r) * PB + n] =
                    make_float2(acc[mt][nt][0], acc[mt][nt][1]);
                *(float2*)&pbuf[(kc * 32 + r + 8) * PB + n] =
                    make_float2(acc[mt][nt][2], acc[mt][nt][3]);
            }
        }
        __syncthreads();
        // ---- reduce 4 K-partials + bias, LSTM cell update, publish h_{t+1} ----
        #pragma unroll
        for (int s = 0; s < 2; s++) {
            int tk = tid + s * 256;
            int row = tk >> 4, j = tk & 15;
            float4 sum = *(float4*)&pbuf[row * PB + j * 4];
            #pragma unroll
            for (int k = 1; k < 4; k++) {
                float4 p = *(float4*)&pbuf[(k * 32 + row) * PB + j * 4];
                sum.x += p.x; sum.y += p.y; sum.z += p.z; sum.w += p.w;
            }
            float pi = sum.x + bias[s][0];
            float pf = sum.y + bias[s][1];
            float pg = sum.z + bias[s][2];
            float po = sum.w + bias[s][3];
            float ii = fsig(pi), ff = fsig(pf), gg = ftanh(pg), oo = fsig(po);
            float cc = cst[s] * ff + ii * gg;
            cst[s] = cc;
            float hn = oo * ftanh(cc);
            g_hf[(t + 1) & 1][row0 + row][colbase + j] = tf32_round(hn);
            if (t == Tt - 1) g_hT[(row0 + row) * Hh + colbase + j] = hn;  // exact
        }
        __syncthreads();                 // all publishes done before release
        if (tid == 0) red_rel(myflag, 1u);
    }
    // reset group flags for deterministic graph replay
    if (cn == 0 && tid == 0) {
        unsigned fin = 8u * (unsigned)(Tt + 1);
        for (int ch = 0; ch < 4; ch++) {
            while (ld_acq(&flags[ch * 32]) < fin) {}
            *(volatile unsigned*)&flags[ch * 32] = 0u;
        }
        __threadfence();
    }
}

// ---------------- phase 3: out = hT @ Wfc^T + bfc, plus hT copy ----------------
__global__ void k_fc(const float* __restrict__ Wfc, const float* __restrict__ bfc,
                     float* __restrict__ out, int out_size) {
    int gid = blockIdx.x * blockDim.x + threadIdx.x;
    int nthr = gridDim.x * blockDim.x;
    for (int i = gid; i < Bb * Hh && i < out_size; i += nthr) out[i] = g_hT[i];
    if (gid < Bb * Oo) {
        int b = gid >> 7, o = gid & 127;
        const float4* hp = (const float4*)&g_hT[b * Hh];
        const float4* wp = (const float4*)&Wfc[(size_t)o * Hh];
        float s = 0.f;
        #pragma unroll 8
        for (int k = 0; k < Hh / 4; k++) {
            float4 hv = hp[k], wv = wp[k];
            s += hv.x * wv.x + hv.y * wv.y + hv.z * wv.z + hv.w * wv.w;
        }
        int idx = Bb * Hh + gid;
        if (idx < out_size) out[idx] = s + bfc[o];
    }
}

// ---------------- launch ----------------
extern "C" void kernel_launch(void* const* d_in, const int* in_sizes, int n_in,
                              void* d_out, int out_size) {
    const float* x   = (const float*)d_in[0];
    const float* Wx  = (const float*)d_in[2];
    const float* bx  = (const float*)d_in[3];
    const float* Wh  = (const float*)d_in[4];
    const float* bh  = (const float*)d_in[5];
    const float* Wfc = (const float*)d_in[8];
    const float* bfc = (const float*)d_in[9];
    float* out = (float*)d_out;

    // 66048 + 34816 + 65536 + 49152 = 215,552 B
    const int smem_rec = RG * S2 * 4 + 4 * 32 * PB * 4 + 8 * 8192 + 8 * 6144;
    cudaFuncSetAttribute(k_rec, cudaFuncAttributeMaxDynamicSharedMemorySize, smem_rec);

    k_rec<<<NG * CG, 256, smem_rec>>>(x, Wx, Wh, bx, bh);
    k_fc<<<256, 256>>>(Wfc, bfc, out, out_size);
}

// round 15
// speedup vs baseline: 1.3169x; 1.3168x over previous
#include <cuda_runtime.h>
#include <cuda_fp16.h>
#include <cstdint>

#define Bb 128
#define Tt 1024
#define Dd 256
#define Hh 512
#define Oo 128
#define G4H 2048

#define NG 4      // batch groups (independent LSTM chains)
#define RG 32     // rows per group
#define CG 32     // CTAs per group (each owns 64 gate cols = 16 h cols)

// ---------------- scratch ----------------
__device__ __half g_xh[(size_t)Bb*Tt*Dd];     // 64 MB  x in fp16
__device__ __half g_wxh[(size_t)G4H*Dd];      // 1 MB   Wx in fp16
__device__ __half g_xgh[(size_t)Tt*Bb*G4H];   // 512 MB precomputed input gates (fp16)
__device__ float  g_hf[2][Bb][Hh];            // h double buffer (tf32-rounded fp32)
__device__ float  g_hT[Bb*Hh];                // final h (exact fp32)
__device__ unsigned g_bar4[NG * 4 * 32];      // per-(group,chunk) flags, 128B apart

// ---------------- PTX helpers ----------------
__device__ __forceinline__ unsigned smem_u32(const void* p) {
    return (unsigned)__cvta_generic_to_shared(p);
}
#define CPA16(dst, src) asm volatile("cp.async.cg.shared.global [%0], [%1], 16;\n" :: "r"(dst), "l"(src))
#define CPA_COMMIT()    asm volatile("cp.async.commit_group;\n")
#define CPA_WAIT(n)     asm volatile("cp.async.wait_group %0;\n" :: "n"(n))

__device__ __forceinline__ void ldm_x4(uint32_t* r, unsigned addr) {
    asm volatile("ldmatrix.sync.aligned.m8n8.x4.shared.b16 {%0,%1,%2,%3}, [%4];"
                 : "=r"(r[0]), "=r"(r[1]), "=r"(r[2]), "=r"(r[3]) : "r"(addr));
}
__device__ __forceinline__ void mma_f16(float* c, const uint32_t* a, uint32_t b0, uint32_t b1) {
    asm volatile("mma.sync.aligned.m16n8k16.row.col.f32.f16.f16.f32 "
                 "{%0,%1,%2,%3}, {%4,%5,%6,%7}, {%8,%9}, {%0,%1,%2,%3};"
                 : "+f"(c[0]), "+f"(c[1]), "+f"(c[2]), "+f"(c[3])
                 : "r"(a[0]), "r"(a[1]), "r"(a[2]), "r"(a[3]), "r"(b0), "r"(b1));
}
__device__ __forceinline__ void mma_tf32(float* c, const uint32_t* a, uint32_t b0, uint32_t b1) {
    asm volatile("mma.sync.aligned.m16n8k8.row.col.f32.tf32.tf32.f32 "
                 "{%0,%1,%2,%3}, {%4,%5,%6,%7}, {%8,%9}, {%0,%1,%2,%3};"
                 : "+f"(c[0]), "+f"(c[1]), "+f"(c[2]), "+f"(c[3])
                 : "r"(a[0]), "r"(a[1]), "r"(a[2]), "r"(a[3]), "r"(b0), "r"(b1));
}
__device__ __forceinline__ uint32_t tf32_bits(float f) {
    uint32_t u; asm("cvt.rna.tf32.f32 %0, %1;" : "=r"(u) : "f"(f)); return u;
}
__device__ __forceinline__ float tf32_round(float f) { return __uint_as_float(tf32_bits(f)); }
__device__ __forceinline__ unsigned ld_acq(const unsigned* p) {
    unsigned v; asm volatile("ld.acquire.gpu.u32 %0, [%1];" : "=r"(v) : "l"(p) : "memory"); return v;
}
__device__ __forceinline__ void red_rel(unsigned* p, unsigned v) {
    asm volatile("red.release.gpu.add.u32 [%0], %1;" :: "l"(p), "r"(v) : "memory");
}
__device__ __forceinline__ float fsig(float x)  { return 1.f / (1.f + __expf(-x)); }
__device__ __forceinline__ float ftanh(float x) { return 2.f / (1.f + __expf(-2.f * x)) - 1.f; }

// ---------------- phase 0: convert x, Wx to fp16 ----------------
__global__ void k_convert(const float* __restrict__ x, const float* __restrict__ Wx) {
    int64_t i = (int64_t)blockIdx.x * blockDim.x + threadIdx.x;
    int64_t stride = (int64_t)gridDim.x * blockDim.x;
    for (int64_t j = i; j < (int64_t)Bb*Tt*Dd / 4; j += stride) {
        float4 v = ((const float4*)x)[j];
        ((__half2*)g_xh)[j*2]   = __floats2half2_rn(v.x, v.y);
        ((__half2*)g_xh)[j*2+1] = __floats2half2_rn(v.z, v.w);
    }
    for (int64_t j = i; j < (int64_t)G4H*Dd / 4; j += stride) {
        float4 v = ((const float4*)Wx)[j];
        ((__half2*)g_wxh)[j*2]   = __floats2half2_rn(v.x, v.y);
        ((__half2*)g_wxh)[j*2+1] = __floats2half2_rn(v.z, v.w);
    }
}

// ---------------- phase 1: xg[t][b][4H] = x @ Wx^T + (bx+bh), fp16 m16n8k16 mma ------
// CTA: one t (M=128 batch), N-tile=128. K=256 in 2 chunks of 128 fp16.
// Full-rate fp16 tensor path, half the instruction count of the tf32 version.
#define S1H 136   // fp16 row stride per chunk: 17 x 16B chunks (odd -> conflict-free)
__global__ void __launch_bounds__(256, 2) k_xg(const float* __restrict__ bx,
                                               const float* __restrict__ bh) {
    extern __shared__ char sm[];
    __half* As = (__half*)sm;                      // [128][136]
    __half* Bs = As + 128 * S1H;                   // [128][136]
    const int tid = threadIdx.x, lane = tid & 31, wid = tid >> 5;
    const int t = blockIdx.y, nb0 = blockIdx.x * 128;
    const int warp_m = wid & 1, warp_n = wid >> 1; // 2x4 warps: M64 x N32 tiles

    float acc[4][4][4] = {};
    #pragma unroll 1
    for (int ck = 0; ck < 2; ck++) {
        if (ck) __syncthreads();
        // A: x rows (fixed t). 128 rows x 16 chunks (128 fp16 = 256 B) = 2048 tasks.
        #pragma unroll
        for (int it = 0; it < 8; it++) {
            int task = tid + it * 256, b = task >> 4, c = task & 15;
            CPA16(smem_u32(As + b * S1H + c * 8),
                  g_xh + ((size_t)b * Tt + t) * Dd + ck * 128 + c * 8);
        }
        // B: Wx rows nb0..nb0+127, same K-chunk
        #pragma unroll
        for (int it = 0; it < 8; it++) {
            int task = tid + it * 256, n = task >> 4, c = task & 15;
            CPA16(smem_u32(Bs + n * S1H + c * 8),
                  g_wxh + (size_t)(nb0 + n) * Dd + ck * 128 + c * 8);
        }
        CPA_COMMIT(); CPA_WAIT(0);
        __syncthreads();

        #pragma unroll
        for (int kl = 0; kl < 8; kl++) {           // 8 k16-steps per chunk
            uint32_t a[4][4];
            #pragma unroll
            for (int mt = 0; mt < 4; mt++) {
                int r = warp_m * 64 + mt * 16 + (lane & 15);
                int c = kl * 16 + ((lane >> 4) << 3);
                ldm_x4(a[mt], smem_u32(As + r * S1H + c));
            }
            uint32_t bfr[4][2];
            #pragma unroll
            for (int ntp = 0; ntp < 2; ntp++) {
                int matrix = lane >> 3;
                int n = warp_n * 32 + ntp * 16 + ((matrix >> 1) << 3) + (lane & 7);
                int kcc = kl * 16 + ((matrix & 1) << 3);
                uint32_t r4[4];
                ldm_x4(r4, smem_u32(Bs + n * S1H + kcc));
                bfr[ntp*2][0] = r4[0];   bfr[ntp*2][1] = r4[1];
                bfr[ntp*2+1][0] = r4[2]; bfr[ntp*2+1][1] = r4[3];
            }
            #pragma unroll
            for (int mt = 0; mt < 4; mt++)
                #pragma unroll
                for (int nt = 0; nt < 4; nt++)
                    mma_f16(acc[mt][nt], a[mt], bfr[nt][0], bfr[nt][1]);
        }
    }
    // epilogue: exact fp32 bias, round to fp16, streaming stores
    const int group = lane >> 2, tc = lane & 3;
    #pragma unroll
    for (int mt = 0; mt < 4; mt++) {
        #pragma unroll
        for (int nt = 0; nt < 4; nt++) {
            int col = nb0 + warp_n * 32 + nt * 8 + tc * 2;
            float b0 = __ldg(&bx[col]) + __ldg(&bh[col]);
            float b1 = __ldg(&bx[col + 1]) + __ldg(&bh[col + 1]);
            int row0 = warp_m * 64 + mt * 16 + group;
            __half2 v0 = __floats2half2_rn(acc[mt][nt][0] + b0, acc[mt][nt][1] + b1);
            __half2 v1 = __floats2half2_rn(acc[mt][nt][2] + b0, acc[mt][nt][3] + b1);
            unsigned u0 = *reinterpret_cast<unsigned*>(&v0);
            unsigned u1 = *reinterpret_cast<unsigned*>(&v1);
            __stcs((unsigned*)&g_xgh[((size_t)t * Bb + row0) * G4H + col], u0);
            __stcs((unsigned*)&g_xgh[((size_t)t * Bb + row0 + 8) * G4H + col], u1);
        }
    }
}

// ---------------- phase 2: grouped LSTM recurrence (R10-verified core, fp16 xg) ------
#define S2 516   // fp32 row stride for h smem: 129 x 16B chunks (odd)
#define PB 72    // pbuf padded row stride
__global__ void __launch_bounds__(256, 1) k_rec(const float* __restrict__ Wh) {
    extern __shared__ char sm[];
    float* hb   = (float*)sm;                      // [32][516]      66048 B
    float* pbuf = hb + RG * S2;                    // [4][32][72]    36864 B
    char*  bfr  = (char*)(pbuf + 4 * 32 * PB);     // 8 x 8192 B =   65536 B
    const int tid = threadIdx.x, lane = tid & 31, wid = tid >> 5;
    const int kc = wid >> 1, tau = wid & 1;        // K-chunk, N-half of this warp
    const int grp = blockIdx.x >> 5, cn = blockIdx.x & 31;
    const int colbase = cn * 16, row0 = grp * RG;
    unsigned* flags  = &g_bar4[grp * 4 * 32];
    unsigned* myflag = &flags[(cn >> 3) * 32];     // chunk this CTA's h slice feeds
    unsigned* kflag  = &flags[kc * 32];            // chunk this warp consumes

    // Build Wh B-fragments once (tf32-rounded); kl 0..7 -> smem, kl 8..15 -> regs.
    uint4 breg[16];
    char* wb = bfr + wid * 8192;
    for (int kl = 0; kl < 16; kl++) {
        #pragma unroll
        for (int h2 = 0; h2 < 2; h2++) {
            uint32_t v[4];
            #pragma unroll
            for (int q = 0; q < 2; q++) {
                int nt = h2 * 2 + q;
                int n = tau * 32 + nt * 8 + (lane >> 2);  // local gate col 0..63
                int jj = n >> 2, gate = n & 3;
                int grow = gate * Hh + colbase + jj;      // Wh global row
                int k = kc * 128 + kl * 8 + (lane & 3);
                const float* wp = Wh + (size_t)grow * Hh;
                v[q*2]   = tf32_bits(wp[k]);
                v[q*2+1] = tf32_bits(wp[k + 4]);
            }
            uint4 u = make_uint4(v[0], v[1], v[2], v[3]);
            if (kl < 8) *(uint4*)(wb + (kl * 2 + h2) * 512 + lane * 16) = u;
            else breg[(kl - 8) * 2 + h2] = u;
        }
    }
    // zero h0 slice, publish chunk readiness
    for (int tk = tid; tk < 512; tk += 256)
        g_hf[0][row0 + (tk >> 4)][colbase + (tk & 15)] = 0.f;
    __syncthreads();
    if (tid == 0) red_rel(myflag, 1u);

    float cst[2] = {0.f, 0.f};                     // c-state per epilogue task

    for (int t = 0; t < Tt; t++) {
        // xg prefetch (fp16) for this thread's epilogue tasks — overlaps the spin
        float xr[2][4];
        {
            const __half* xgt = g_xgh + (size_t)t * Bb * G4H;
            #pragma unroll
            for (int s = 0; s < 2; s++) {
                int tk = tid + s * 256;
                int row = row0 + (tk >> 4), j = colbase + (tk & 15);
                const __half* p = xgt + (size_t)row * G4H + j;
                #pragma unroll
                for (int gt = 0; gt < 4; gt++) {
                    unsigned short u = __ldcs((const unsigned short*)(p + gt * Hh));
                    xr[s][gt] = __half2float(__ushort_as_half(u));
                }
            }
        }
        // per-warp spin: only this warp's K-chunk producers (8 CTAs)
        if (lane == 0) {
            unsigned tgt = 8u * (unsigned)(t + 1);
            while (ld_acq(kflag) < tgt) {}
        }
        __syncwarp();
        // stage this warp's half of chunk kc (8 KB); partner-sync via named barrier
        {
            const float* hsrc = &g_hf[t & 1][row0][0];
            #pragma unroll
            for (int i = 0; i < 16; i++) {
                int row = i * 2 + (lane >> 4);
                int cw = kc * 128 + (tau * 16 + (lane & 15)) * 4;
                CPA16(smem_u32(hb + row * S2 + cw), hsrc + (size_t)row * Hh + cw);
            }
            CPA_COMMIT(); CPA_WAIT(0);
            asm volatile("bar.sync %0, 64;" :: "r"(1 + kc) : "memory");
        }
        // MMA: M32 x N32(tau) x K128(kc)
        float acc[2][4][4] = {};
        #pragma unroll
        for (int kl = 0; kl < 16; kl++) {
            uint4 q0, q1;
            if (kl < 8) {
                q0 = *(const uint4*)(wb + (kl * 2 + 0) * 512 + lane * 16);
                q1 = *(const uint4*)(wb + (kl * 2 + 1) * 512 + lane * 16);
            } else {
                q0 = breg[(kl - 8) * 2];
                q1 = breg[(kl - 8) * 2 + 1];
            }
            uint32_t a0[4], a1[4];
            int c = kc * 128 + kl * 8 + (lane >> 4) * 4;
            int rr = (lane & 7) + ((lane >> 3) & 1) * 8;
            ldm_x4(a0, smem_u32(hb + rr * S2 + c));
            ldm_x4(a1, smem_u32(hb + (rr + 16) * S2 + c));
            mma_tf32(acc[0][0], a0, q0.x, q0.y);
            mma_tf32(acc[0][1], a0, q0.z, q0.w);
            mma_tf32(acc[0][2], a0, q1.x, q1.y);
            mma_tf32(acc[0][3], a0, q1.z, q1.w);
            mma_tf32(acc[1][0], a1, q0.x, q0.y);
            mma_tf32(acc[1][1], a1, q0.z, q0.w);
            mma_tf32(acc[1][2], a1, q1.x, q1.y);
            mma_tf32(acc[1][3], a1, q1.z, q1.w);
        }
        // store K-partials in logical (row, gatecol) layout
        #pragma unroll
        for (int mt = 0; mt < 2; mt++) {
            #pragma unroll
            for (int nt = 0; nt < 4; nt++) {
                int r = mt * 16 + (lane >> 2);
                int n = tau * 32 + nt * 8 + (lane & 3) * 2;
                *(float2*)&pbuf[(kc * 32 + r) * PB + n] =
                    make_float2(acc[mt][nt][0], acc[mt][nt][1]);
                *(float2*)&pbuf[(kc * 32 + r + 8) * PB + n] =
                    make_float2(acc[mt][nt][2], acc[mt][nt][3]);
            }
        }
        __syncthreads();
        // reduce 4 K-partials + LSTM cell update per task, publish h_{t+1}
        #pragma unroll
        for (int s = 0; s < 2; s++) {
            int tk = tid + s * 256;
            int row = tk >> 4, j = tk & 15;
            float4 sum = *(float4*)&pbuf[row * PB + j * 4];
            #pragma unroll
            for (int k = 1; k < 4; k++) {
                float4 p = *(float4*)&pbuf[(k * 32 + row) * PB + j * 4];
                sum.x += p.x; sum.y += p.y; sum.z += p.z; sum.w += p.w;
            }
            float pi = sum.x + xr[s][0];
            float pf = sum.y + xr[s][1];
            float pg = sum.z + xr[s][2];
            float po = sum.w + xr[s][3];
            float ii = fsig(pi), ff = fsig(pf), gg = ftanh(pg), oo = fsig(po);
            float cc = cst[s] * ff + ii * gg;
            cst[s] = cc;
            float hn = oo * ftanh(cc);
            g_hf[(t + 1) & 1][row0 + row][colbase + j] = tf32_round(hn);
            if (t == Tt - 1) g_hT[(row0 + row) * Hh + colbase + j] = hn;  // exact
        }
        __syncthreads();                 // all publishes done before release
        if (tid == 0) red_rel(myflag, 1u);
    }
    // reset group flags for deterministic graph replay
    if (cn == 0 && tid == 0) {
        unsigned fin = 8u * (unsigned)(Tt + 1);
        for (int ch = 0; ch < 4; ch++) {
            while (ld_acq(&flags[ch * 32]) < fin) {}
            *(volatile unsigned*)&flags[ch * 32] = 0u;
        }
        __threadfence();
    }
}

// ---------------- phase 3: out = hT @ Wfc^T + bfc, plus hT copy ----------------
__global__ void k_fc(const float* __restrict__ Wfc, const float* __restrict__ bfc,
                     float* __restrict__ out, int out_size) {
    int gid = blockIdx.x * blockDim.x + threadIdx.x;
    int nthr = gridDim.x * blockDim.x;
    for (int i = gid; i < Bb * Hh && i < out_size; i += nthr) out[i] = g_hT[i];
    if (gid < Bb * Oo) {
        int b = gid >> 7, o = gid & 127;
        const float4* hp = (const float4*)&g_hT[b * Hh];
        const float4* wp = (const float4*)&Wfc[(size_t)o * Hh];
        float s = 0.f;
        #pragma unroll 8
        for (int k = 0; k < Hh / 4; k++) {
            float4 hv = hp[k], wv = wp[k];
            s += hv.x * wv.x + hv.y * wv.y + hv.z * wv.z + hv.w * wv.w;
        }
        int idx = Bb * Hh + gid;
        if (idx < out_size) out[idx] = s + bfc[o];
    }
}

// ---------------- launch ----------------
extern "C" void kernel_launch(void* const* d_in, const int* in_sizes, int n_in,
                              void* d_out, int out_size) {
    const float* x   = (const float*)d_in[0];
    const float* Wx  = (const float*)d_in[2];
    const float* bx  = (const float*)d_in[3];
    const float* Wh  = (const float*)d_in[4];
    const float* bh  = (const float*)d_in[5];
    const float* Wfc = (const float*)d_in[8];
    const float* bfc = (const float*)d_in[9];
    float* out = (float*)d_out;

    const int smem_xg  = 2 * 128 * S1H * 2;                        // 69,632 B (2 CTAs/SM)
    const int smem_rec = RG * S2 * 4 + 4 * 32 * PB * 4 + 8 * 8192; // 168,448 B
    cudaFuncSetAttribute(k_xg,  cudaFuncAttributeMaxDynamicSharedMemorySize, smem_xg);
    cudaFuncSetAttribute(k_rec, cudaFuncAttributeMaxDynamicSharedMemorySize, smem_rec);

    k_convert<<<1024, 256>>>(x, Wx);
    k_xg<<<dim3(16, 1024), 256, smem_xg>>>(bx, bh);
    k_rec<<<NG * CG, 256, smem_rec>>>(Wh);
    k_fc<<<256, 256>>>(Wfc, bfc, out, out_size);
}

// round 16
// speedup vs baseline: 1.7256x; 1.3103x over previous
#include <cuda_runtime.h>
#include <cuda_fp16.h>
#include <cstdint>

#define Bb 128
#define Tt 1024
#define Dd 256
#define Hh 512
#define Oo 128
#define G4H 2048

#define NG 4      // batch groups (independent LSTM chains)
#define RG 32     // rows per group
#define CG 32     // CTAs per group (each owns 64 gate cols = 16 h cols)

// ---------------- scratch ----------------
__device__ __half g_xh[(size_t)Bb*Tt*Dd];     // 64 MB  x in fp16
__device__ __half g_wxh[(size_t)G4H*Dd];      // 1 MB   Wx in fp16
__device__ __half g_xgh[(size_t)Tt*Bb*G4H];   // 512 MB precomputed input gates (fp16)
__device__ __align__(16) __half g_hfh[2][Bb][Hh];  // h double buffer (fp16)
__device__ float  g_hT[Bb*Hh];                // final h (exact fp32)
__device__ unsigned g_bar4[NG * 4 * 32];      // per-(group,chunk) flags, 128B apart

// ---------------- PTX helpers ----------------
__device__ __forceinline__ unsigned smem_u32(const void* p) {
    return (unsigned)__cvta_generic_to_shared(p);
}
#define CPA16(dst, src) asm volatile("cp.async.cg.shared.global [%0], [%1], 16;\n" :: "r"(dst), "l"(src))
#define CPA_COMMIT()    asm volatile("cp.async.commit_group;\n")
#define CPA_WAIT(n)     asm volatile("cp.async.wait_group %0;\n" :: "n"(n))

__device__ __forceinline__ void ldm_x4(uint32_t* r, unsigned addr) {
    asm volatile("ldmatrix.sync.aligned.m8n8.x4.shared.b16 {%0,%1,%2,%3}, [%4];"
                 : "=r"(r[0]), "=r"(r[1]), "=r"(r[2]), "=r"(r[3]) : "r"(addr));
}
__device__ __forceinline__ void mma_f16(float* c, const uint32_t* a, uint32_t b0, uint32_t b1) {
    asm volatile("mma.sync.aligned.m16n8k16.row.col.f32.f16.f16.f32 "
                 "{%0,%1,%2,%3}, {%4,%5,%6,%7}, {%8,%9}, {%0,%1,%2,%3};"
                 : "+f"(c[0]), "+f"(c[1]), "+f"(c[2]), "+f"(c[3])
                 : "r"(a[0]), "r"(a[1]), "r"(a[2]), "r"(a[3]), "r"(b0), "r"(b1));
}
__device__ __forceinline__ unsigned ld_acq(const unsigned* p) {
    unsigned v; asm volatile("ld.acquire.gpu.u32 %0, [%1];" : "=r"(v) : "l"(p) : "memory"); return v;
}
__device__ __forceinline__ void red_rel(unsigned* p, unsigned v) {
    asm volatile("red.release.gpu.add.u32 [%0], %1;" :: "l"(p), "r"(v) : "memory");
}
__device__ __forceinline__ float fsig(float x)  { return 1.f / (1.f + __expf(-x)); }
__device__ __forceinline__ float ftanh(float x) { return 2.f / (1.f + __expf(-2.f * x)) - 1.f; }

// ---------------- phase 0: convert x, Wx to fp16 ----------------
__global__ void k_convert(const float* __restrict__ x, const float* __restrict__ Wx) {
    int64_t i = (int64_t)blockIdx.x * blockDim.x + threadIdx.x;
    int64_t stride = (int64_t)gridDim.x * blockDim.x;
    for (int64_t j = i; j < (int64_t)Bb*Tt*Dd / 4; j += stride) {
        float4 v = ((const float4*)x)[j];
        ((__half2*)g_xh)[j*2]   = __floats2half2_rn(v.x, v.y);
        ((__half2*)g_xh)[j*2+1] = __floats2half2_rn(v.z, v.w);
    }
    for (int64_t j = i; j < (int64_t)G4H*Dd / 4; j += stride) {
        float4 v = ((const float4*)Wx)[j];
        ((__half2*)g_wxh)[j*2]   = __floats2half2_rn(v.x, v.y);
        ((__half2*)g_wxh)[j*2+1] = __floats2half2_rn(v.z, v.w);
    }
}

// ---------------- phase 1: xg[t][b][4H] = x @ Wx^T + (bx+bh), fp16 m16n8k16 mma ------
// (unchanged from R15 — verified passing)
#define S1H 136   // fp16 row stride per chunk: 17 x 16B chunks (odd -> conflict-free)
__global__ void __launch_bounds__(256, 2) k_xg(const float* __restrict__ bx,
                                               const float* __restrict__ bh) {
    extern __shared__ char sm[];
    __half* As = (__half*)sm;                      // [128][136]
    __half* Bs = As + 128 * S1H;                   // [128][136]
    const int tid = threadIdx.x, lane = tid & 31, wid = tid >> 5;
    const int t = blockIdx.y, nb0 = blockIdx.x * 128;
    const int warp_m = wid & 1, warp_n = wid >> 1; // 2x4 warps: M64 x N32 tiles

    float acc[4][4][4] = {};
    #pragma unroll 1
    for (int ck = 0; ck < 2; ck++) {
        if (ck) __syncthreads();
        #pragma unroll
        for (int it = 0; it < 8; it++) {
            int task = tid + it * 256, b = task >> 4, c = task & 15;
            CPA16(smem_u32(As + b * S1H + c * 8),
                  g_xh + ((size_t)b * Tt + t) * Dd + ck * 128 + c * 8);
        }
        #pragma unroll
        for (int it = 0; it < 8; it++) {
            int task = tid + it * 256, n = task >> 4, c = task & 15;
            CPA16(smem_u32(Bs + n * S1H + c * 8),
                  g_wxh + (size_t)(nb0 + n) * Dd + ck * 128 + c * 8);
        }
        CPA_COMMIT(); CPA_WAIT(0);
        __syncthreads();

        #pragma unroll
        for (int kl = 0; kl < 8; kl++) {           // 8 k16-steps per chunk
            uint32_t a[4][4];
            #pragma unroll
            for (int mt = 0; mt < 4; mt++) {
                int r = warp_m * 64 + mt * 16 + (lane & 15);
                int c = kl * 16 + ((lane >> 4) << 3);
                ldm_x4(a[mt], smem_u32(As + r * S1H + c));
            }
            uint32_t bfr[4][2];
            #pragma unroll
            for (int ntp = 0; ntp < 2; ntp++) {
                int matrix = lane >> 3;
                int n = warp_n * 32 + ntp * 16 + ((matrix >> 1) << 3) + (lane & 7);
                int kcc = kl * 16 + ((matrix & 1) << 3);
                uint32_t r4[4];
                ldm_x4(r4, smem_u32(Bs + n * S1H + kcc));
                bfr[ntp*2][0] = r4[0];   bfr[ntp*2][1] = r4[1];
                bfr[ntp*2+1][0] = r4[2]; bfr[ntp*2+1][1] = r4[3];
            }
            #pragma unroll
            for (int mt = 0; mt < 4; mt++)
                #pragma unroll
                for (int nt = 0; nt < 4; nt++)
                    mma_f16(acc[mt][nt], a[mt], bfr[nt][0], bfr[nt][1]);
        }
    }
    const int group = lane >> 2, tc = lane & 3;
    #pragma unroll
    for (int mt = 0; mt < 4; mt++) {
        #pragma unroll
        for (int nt = 0; nt < 4; nt++) {
            int col = nb0 + warp_n * 32 + nt * 8 + tc * 2;
            float b0 = __ldg(&bx[col]) + __ldg(&bh[col]);
            float b1 = __ldg(&bx[col + 1]) + __ldg(&bh[col + 1]);
            int row0 = warp_m * 64 + mt * 16 + group;
            __half2 v0 = __floats2half2_rn(acc[mt][nt][0] + b0, acc[mt][nt][1] + b1);
            __half2 v1 = __floats2half2_rn(acc[mt][nt][2] + b0, acc[mt][nt][3] + b1);
            unsigned u0 = *reinterpret_cast<unsigned*>(&v0);
            unsigned u1 = *reinterpret_cast<unsigned*>(&v1);
            __stcs((unsigned*)&g_xgh[((size_t)t * Bb + row0) * G4H + col], u0);
            __stcs((unsigned*)&g_xgh[((size_t)t * Bb + row0 + 8) * G4H + col], u1);
        }
    }
}

// ---------------- phase 2: grouped LSTM recurrence — full fp16 datapath --------------
// 4 groups x 32 CTAs. CTA: M=32 rows, N=64 gate cols, K=512 over 4 warp K-chunks.
// h stored/broadcast/staged in fp16 (bytes halve); Wh fragments fp16, ALL in registers
// (64 regs/thread; zero smem traffic). MMA = fp16 m16n8k16 full-rate: per warp-step
// 8 k-iterations x (2 ldmatrix + 8 mma). Flags/sync/epilogue identical to R10 core.
#define S2H 520   // fp16 row stride for h smem: 65 x 16B chunks (odd -> conflict-free)
#define PB 72     // pbuf padded row stride (fp32)
__global__ void __launch_bounds__(256, 1) k_rec(const float* __restrict__ Wh) {
    extern __shared__ char sm[];
    __half* hb  = (__half*)sm;                     // [32][520] fp16   33280 B
    float* pbuf = (float*)(sm + RG * S2H * 2);     // [4][32][72] fp32 36864 B
    const int tid = threadIdx.x, lane = tid & 31, wid = tid >> 5;
    const int kc = wid >> 1, tau = wid & 1;        // K-chunk, N-half of this warp
    const int grp = blockIdx.x >> 5, cn = blockIdx.x & 31;
    const int colbase = cn * 16, row0 = grp * RG;
    unsigned* flags  = &g_bar4[grp * 4 * 32];
    unsigned* myflag = &flags[(cn >> 3) * 32];     // chunk this CTA's h slice feeds
    unsigned* kflag  = &flags[kc * 32];            // chunk this warp consumes

    // Build Wh B-fragments once (fp16, packed pairs) — ALL in registers.
    // m16n8k16 B layout: b0 holds W[k0+(lane&3)*2 + {0,1}][n], b1 the k0+8 partner.
    uint32_t breg[8][8];
    #pragma unroll
    for (int kl = 0; kl < 8; kl++) {
        #pragma unroll
        for (int nt = 0; nt < 4; nt++) {
            int n = tau * 32 + nt * 8 + (lane >> 2);      // local gate col 0..63
            int jj = n >> 2, gate = n & 3;
            const float* wp = Wh + (size_t)(gate * Hh + colbase + jj) * Hh;
            int k0 = kc * 128 + kl * 16 + (lane & 3) * 2;
            __half2 b0 = __floats2half2_rn(wp[k0], wp[k0 + 1]);
            __half2 b1 = __floats2half2_rn(wp[k0 + 8], wp[k0 + 9]);
            breg[kl][nt*2]   = *reinterpret_cast<uint32_t*>(&b0);
            breg[kl][nt*2+1] = *reinterpret_cast<uint32_t*>(&b1);
        }
    }
    // zero h0 slice, publish chunk readiness
    for (int tk = tid; tk < 512; tk += 256)
        g_hfh[0][row0 + (tk >> 4)][colbase + (tk & 15)] = __float2half(0.f);
    __syncthreads();
    if (tid == 0) red_rel(myflag, 1u);

    float cst[2] = {0.f, 0.f};                     // c-state per epilogue task

    for (int t = 0; t < Tt; t++) {
        // xg prefetch (fp16) for this thread's epilogue tasks — overlaps the spin
        float xr[2][4];
        {
            const __half* xgt = g_xgh + (size_t)t * Bb * G4H;
            #pragma unroll
            for (int s = 0; s < 2; s++) {
                int tk = tid + s * 256;
                int row = row0 + (tk >> 4), j = colbase + (tk & 15);
                const __half* p = xgt + (size_t)row * G4H + j;
                #pragma unroll
                for (int gt = 0; gt < 4; gt++) {
                    unsigned short u = __ldcs((const unsigned short*)(p + gt * Hh));
                    xr[s][gt] = __half2float(__ushort_as_half(u));
                }
            }
        }
        // per-warp spin: only this warp's K-chunk producers (8 CTAs)
        if (lane == 0) {
            unsigned tgt = 8u * (unsigned)(t + 1);
            while (ld_acq(kflag) < tgt) {}
        }
        __syncwarp();
        // stage this warp's half of h chunk kc (4 KB fp16); partner-sync
        {
            const __half* hsrc = &g_hfh[t & 1][row0][0];
            #pragma unroll
            for (int i = 0; i < 8; i++) {
                int task = lane + i * 32;
                int row = task >> 3, c8 = task & 7;
                int off = kc * 128 + tau * 64 + c8 * 8;
                CPA16(smem_u32(hb + row * S2H + off), hsrc + (size_t)row * Hh + off);
            }
            CPA_COMMIT(); CPA_WAIT(0);
            asm volatile("bar.sync %0, 64;" :: "r"(1 + kc) : "memory");
        }
        // MMA: M32 x N32(tau) x K128(kc), fp16 m16n8k16
        float acc[2][4][4] = {};
        #pragma unroll
        for (int kl = 0; kl < 8; kl++) {
            uint32_t a0[4], a1[4];
            int c = kc * 128 + kl * 16 + ((lane >> 4) << 3);
            int rr = lane & 15;
            ldm_x4(a0, smem_u32(hb + rr * S2H + c));
            ldm_x4(a1, smem_u32(hb + (rr + 16) * S2H + c));
            #pragma unroll
            for (int nt = 0; nt < 4; nt++) {
                mma_f16(acc[0][nt], a0, breg[kl][nt*2], breg[kl][nt*2+1]);
                mma_f16(acc[1][nt], a1, breg[kl][nt*2], breg[kl][nt*2+1]);
            }
        }
        // store K-partials in logical (row, gatecol) layout
        #pragma unroll
        for (int mt = 0; mt < 2; mt++) {
            #pragma unroll
            for (int nt = 0; nt < 4; nt++) {
                int r = mt * 16 + (lane >> 2);
                int n = tau * 32 + nt * 8 + (lane & 3) * 2;
                *(float2*)&pbuf[(kc * 32 + r) * PB + n] =
                    make_float2(acc[mt][nt][0], acc[mt][nt][1]);
                *(float2*)&pbuf[(kc * 32 + r + 8) * PB + n] =
                    make_float2(acc[mt][nt][2], acc[mt][nt][3]);
            }
        }
        __syncthreads();
        // reduce 4 K-partials + LSTM cell update per task, publish h_{t+1} (fp16)
        #pragma unroll
        for (int s = 0; s < 2; s++) {
            int tk = tid + s * 256;
            int row = tk >> 4, j = tk & 15;
            float4 sum = *(float4*)&pbuf[row * PB + j * 4];
            #pragma unroll
            for (int k = 1; k < 4; k++) {
                float4 p = *(float4*)&pbuf[(k * 32 + row) * PB + j * 4];
                sum.x += p.x; sum.y += p.y; sum.z += p.z; sum.w += p.w;
            }
            float pi = sum.x + xr[s][0];
            float pf = sum.y + xr[s][1];
            float pg = sum.z + xr[s][2];
            float po = sum.w + xr[s][3];
            float ii = fsig(pi), ff = fsig(pf), gg = ftanh(pg), oo = fsig(po);
            float cc = cst[s] * ff + ii * gg;
            cst[s] = cc;
            float hn = oo * ftanh(cc);
            g_hfh[(t + 1) & 1][row0 + row][colbase + j] = __float2half_rn(hn);
            if (t == Tt - 1) g_hT[(row0 + row) * Hh + colbase + j] = hn;  // exact
        }
        __syncthreads();                 // all publishes done before release
        if (tid == 0) red_rel(myflag, 1u);
    }
    // reset group flags for deterministic graph replay
    if (cn == 0 && tid == 0) {
        unsigned fin = 8u * (unsigned)(Tt + 1);
        for (int ch = 0; ch < 4; ch++) {
            while (ld_acq(&flags[ch * 32]) < fin) {}
            *(volatile unsigned*)&flags[ch * 32] = 0u;
        }
        __threadfence();
    }
}

// ---------------- phase 3: out = hT @ Wfc^T + bfc, plus hT copy ----------------
__global__ void k_fc(const float* __restrict__ Wfc, const float* __restrict__ bfc,
                     float* __restrict__ out, int out_size) {
    int gid = blockIdx.x * blockDim.x + threadIdx.x;
    int nthr = gridDim.x * blockDim.x;
    for (int i = gid; i < Bb * Hh && i < out_size; i += nthr) out[i] = g_hT[i];
    if (gid < Bb * Oo) {
        int b = gid >> 7, o = gid & 127;
        const float4* hp = (const float4*)&g_hT[b * Hh];
        const float4* wp = (const float4*)&Wfc[(size_t)o * Hh];
        float s = 0.f;
        #pragma unroll 8
        for (int k = 0; k < Hh / 4; k++) {
            float4 hv = hp[k], wv = wp[k];
            s += hv.x * wv.x + hv.y * wv.y + hv.z * wv.z + hv.w * wv.w;
        }
        int idx = Bb * Hh + gid;
        if (idx < out_size) out[idx] = s + bfc[o];
    }
}

// ---------------- launch ----------------
extern "C" void kernel_launch(void* const* d_in, const int* in_sizes, int n_in,
                              void* d_out, int out_size) {
    const float* x   = (const float*)d_in[0];
    const float* Wx  = (const float*)d_in[2];
    const float* bx  = (const float*)d_in[3];
    const float* Wh  = (const float*)d_in[4];
    const float* bh  = (const float*)d_in[5];
    const float* Wfc = (const float*)d_in[8];
    const float* bfc = (const float*)d_in[9];
    float* out = (float*)d_out;

    const int smem_xg  = 2 * 128 * S1H * 2;              // 69,632 B (2 CTAs/SM)
    const int smem_rec = RG * S2H * 2 + 4 * 32 * PB * 4; // 70,144 B
    cudaFuncSetAttribute(k_xg,  cudaFuncAttributeMaxDynamicSharedMemorySize, smem_xg);
    cudaFuncSetAttribute(k_rec, cudaFuncAttributeMaxDynamicSharedMemorySize, smem_rec);

    k_convert<<<1024, 256>>>(x, Wx);
    k_xg<<<dim3(16, 1024), 256, smem_xg>>>(bx, bh);
    k_rec<<<NG * CG, 256, smem_rec>>>(Wh);
    k_fc<<<256, 256>>>(Wfc, bfc, out, out_size);
}